// round 7
// baseline (speedup 1.0000x reference)
#include <cuda_runtime.h>
#include <cuda_bf16.h>
#include <math.h>
#include <stdint.h>

constexpr int Dm = 1024;   // dim == seq len L
constexpr int Ns = 16;     // SSM state size
constexpr int KC = 3 * Dm; // conv GEMM K = 3072

typedef __nv_bfloat16 bf16;

// ---------------- scratch (static device globals: allocation-free) ----------
__device__ bf16 g_xhi[2 * Dm * Dm], g_xlo[2 * Dm * Dm];
__device__ bf16 g_Wphi[Dm * Dm],   g_Wplo[Dm * Dm];
__device__ bf16 g_cwhi[Dm * KC],   g_cwlo[Dm * KC];
__device__ bf16 g_WdThi[Dm * Dm],  g_WdTlo[Dm * Dm];
__device__ float g_p0[Dm * Dm];
__device__ bf16 g_xghi[Dm * Dm],   g_xglo[Dm * Dm];
__device__ bf16 g_cBhi[Dm * KC],   g_cBlo[Dm * KC];
__device__ float g_xc[Dm * Dm];
__device__ bf16 g_xchi[Dm * Dm],   g_xclo[Dm * Dm];
__device__ float g_delta[Dm * Dm];
__device__ float g_q[Dm * Dm];     // exp(-delta), from delta epilogue
__device__ float g_Bm[Dm * Ns], g_Cm[Dm * Ns];
__device__ bf16 g_yhi[Dm * Dm],    g_ylo[Dm * Dm];
__device__ bf16 g_thi[Dm * Dm],    g_tlo[Dm * Dm];

__device__ __forceinline__ float sigmoidf_(float x) {
    return 1.0f / (1.0f + expf(-x));
}

__device__ __forceinline__ uint32_t smem_u32(const void* p) {
    uint32_t a;
    asm("{ .reg .u64 t; cvta.to.shared.u64 t, %1; cvt.u32.u64 %0, t; }" : "=r"(a) : "l"(p));
    return a;
}

#define SWZ(x) ((x) ^ (((x) >> 3) & 0x70))

__device__ __forceinline__ void cpa16(uint32_t dst, const void* src) {
    asm volatile("cp.async.cg.shared.global [%0], [%1], 16;" :: "r"(dst), "l"(src));
}

#define MMA_BF16(c, a, b0, b1)                                                   \
    asm volatile(                                                                \
        "mma.sync.aligned.m16n8k16.row.col.f32.bf16.bf16.f32 "                   \
        "{%0,%1,%2,%3},{%4,%5,%6,%7},{%8,%9},{%0,%1,%2,%3};"                     \
        : "+f"(c[0]), "+f"(c[1]), "+f"(c[2]), "+f"(c[3])                         \
        : "r"(a[0]), "r"(a[1]), "r"(a[2]), "r"(a[3]), "r"(b0), "r"(b1))

#define LDSM_X4(r0, r1, r2, r3, addr)                                            \
    asm volatile("ldmatrix.sync.aligned.m8n8.x4.shared.b16 {%0,%1,%2,%3}, [%4];" \
        : "=r"(r0), "=r"(r1), "=r"(r2), "=r"(r3) : "r"(addr))

// FMA-only exp (t <= 0 expected); no MUFU.
__device__ __forceinline__ float exp_fma(float t) {
    float z = t * 1.44269504f;
    float r = rintf(z);
    r = fmaxf(r, -126.0f);
    float f = z - r;
    float p = 1.33335581e-3f;
    p = fmaf(p, f, 9.61812910e-3f);
    p = fmaf(p, f, 5.55041086e-2f);
    p = fmaf(p, f, 2.40226507e-1f);
    p = fmaf(p, f, 6.93147182e-1f);
    p = fmaf(p, f, 1.0f);
    return p * __int_as_float(((int)r + 127) << 23);
}

// ---------------- fp32 -> (hi,lo) bf16 split (vectorized 16B stores) --------
__global__ void __launch_bounds__(256) split_k(const float* __restrict__ in,
                                               bf16* __restrict__ hi,
                                               bf16* __restrict__ lo, int n) {
    int i = (blockIdx.x * 256 + threadIdx.x) * 8;
    if (i >= n) return;
    float4 v0 = *(const float4*)(in + i);
    float4 v1 = *(const float4*)(in + i + 4);
    float vv[8] = {v0.x, v0.y, v0.z, v0.w, v1.x, v1.y, v1.z, v1.w};
    __nv_bfloat162 hb[4], lb[4];
#pragma unroll
    for (int j = 0; j < 4; j++) {
        bf16 h0 = __float2bfloat16(vv[2 * j]);
        bf16 h1 = __float2bfloat16(vv[2 * j + 1]);
        hb[j].x = h0; hb[j].y = h1;
        lb[j].x = __float2bfloat16(vv[2 * j] - __bfloat162float(h0));
        lb[j].y = __float2bfloat16(vv[2 * j + 1] - __bfloat162float(h1));
    }
    *(int4*)(hi + i) = *(int4*)hb;
    *(int4*)(lo + i) = *(int4*)lb;
}

// ---------------- transpose + split (for W_delta) ---------------------------
__global__ void __launch_bounds__(256) transpose_split_k(const float* __restrict__ In,
                                                         bf16* __restrict__ hi,
                                                         bf16* __restrict__ lo) {
    __shared__ float t[32][33];
    int x0 = blockIdx.x * 32, y0 = blockIdx.y * 32;
    int tx = threadIdx.x;
    for (int j = threadIdx.y; j < 32; j += 8)
        t[j][tx] = In[(y0 + j) * Dm + x0 + tx];
    __syncthreads();
    for (int j = threadIdx.y; j < 32; j += 8) {
        float v = t[tx][j];
        bf16 h = __float2bfloat16(v);
        size_t idx = (size_t)(x0 + j) * Dm + y0 + tx;
        hi[idx] = h;
        lo[idx] = __float2bfloat16(v - __bfloat162float(h));
    }
}

// ---------------- build conv B matrix: B[d, i*3+kk] = p0[i, d-1+kk] ----------
__global__ void __launch_bounds__(256) conv_b_build(const float* __restrict__ P0,
                                                    bf16* __restrict__ hi,
                                                    bf16* __restrict__ lo) {
    __shared__ float Xs[32][35];
    int d0 = blockIdx.x * 32, i0 = blockIdx.y * 32;
    int tid = threadIdx.x;
    for (int idx = tid; idx < 32 * 34; idx += 256) {
        int r = idx / 34, c = idx % 34;
        int gd = d0 - 1 + c;
        Xs[r][c] = (gd >= 0 && gd < Dm) ? P0[(size_t)(i0 + r) * Dm + gd] : 0.0f;
    }
    __syncthreads();
    int i = tid & 31;
    for (int dl = tid >> 5; dl < 32; dl += 8) {
        size_t base = (size_t)(d0 + dl) * KC + (size_t)(i0 + i) * 3;
#pragma unroll
        for (int kk = 0; kk < 3; kk++) {
            float x = Xs[i][dl + kk];
            bf16 h = __float2bfloat16(x);
            hi[base + kk] = h;
            lo[base + kk] = __float2bfloat16(x - __bfloat162float(h));
        }
    }
}

// ---------------- bf16-split HMMA GEMM, 512 threads, deep pipeline -----------
// C[m,n] = sum_k A[m,k]*B[n,k]; A=Ah+Al, B=Bh+Bl; C ~= Ah*Bh + Ah*Bl + Al*Bh.
// CTA tile TM x TN, K-block 64, NBUF buffers, one barrier per stage.
// 16 warps: WARPS_M x (16/WARPS_M); warp tile 32 x WN.
template <int TM, int TN, int EPI, bool BIASROW, bool WF32, bool WSPLIT, bool DUAL, bool WQ>
__global__ void __launch_bounds__(512, 1)
gemm_mma(const bf16* __restrict__ Ah, const bf16* __restrict__ Al,
         const bf16* __restrict__ Bh, const bf16* __restrict__ Bl,
         const float* __restrict__ bias,
         float* __restrict__ Cf, bf16* __restrict__ Chi, bf16* __restrict__ Clo,
         float* __restrict__ Cq,
         int Nn, int K)
{
    constexpr int OFF_AL = TM * 128;
    constexpr int OFF_BH = TM * 256;
    constexpr int BHL = TN * 128;
    constexpr int STAGEB = (TM + TN) * 256;
    constexpr int NBUF = (STAGEB >= 65536) ? 3 : 4;
    constexpr int DEPTH = NBUF - 1;
    constexpr int WARPS_M = TM / 32;
    constexpr int WN = TN / (16 / WARPS_M);
    constexpr int NG = WN / 16;
    constexpr int NJ = WN / 8;

    extern __shared__ __align__(1024) char dyns[];
    const int tid = threadIdx.x;
    const int lane = tid & 31, warp = tid >> 5;
    const int m0 = blockIdx.y * TM, n0 = blockIdx.x * TN;
    const uint32_t dbase = smem_u32(dyns);
    const int S = K >> 6;

    float acc[2][NJ][4];
#pragma unroll
    for (int a = 0; a < 2; a++)
#pragma unroll
        for (int b = 0; b < NJ; b++)
#pragma unroll
            for (int c = 0; c < 4; c++) acc[a][b][c] = 0.0f;

    auto load_stage = [&](int s) {
        const uint32_t sb = dbase + (s % NBUF) * STAGEB;
        const int k0 = s << 6;
#pragma unroll
        for (int i = 0; i < TM * 8 / 512; i++) {
            int q = tid + (i << 9);
            int r = q >> 3, c = q & 7;
            uint32_t so = SWZ((uint32_t)(r * 128 + c * 16));
            size_t ga = (size_t)(m0 + r) * K + k0 + c * 8;
            cpa16(sb + so, Ah + ga);
            cpa16(sb + OFF_AL + so, Al + ga);
        }
#pragma unroll
        for (int i = 0; i < TN * 8 / 512; i++) {
            int q = tid + (i << 9);
            int r = q >> 3, c = q & 7;
            uint32_t so = SWZ((uint32_t)(r * 128 + c * 16));
            size_t gb = (size_t)(n0 + r) * K + k0 + c * 8;
            cpa16(sb + OFF_BH + so, Bh + gb);
            cpa16(sb + OFF_BH + BHL + so, Bl + gb);
        }
        asm volatile("cp.async.commit_group;" ::: "memory");
    };

#pragma unroll
    for (int s = 0; s < DEPTH; s++) load_stage(s);

    const int wm = (warp % WARPS_M) * 32, wn = (warp / WARPS_M) * WN;
    const uint32_t frow = (lane & 7) + ((lane >> 3) & 1) * 8;
    const uint32_t fxor = (frow & 7) << 4;
    const uint32_t fcol = (lane >> 4) << 4;

    for (int s = 0; s < S; s++) {
        asm volatile("cp.async.wait_group %0;" :: "n"(DEPTH - 1) : "memory");
        __syncthreads();
        if (s + DEPTH < S) load_stage(s + DEPTH);
        else asm volatile("cp.async.commit_group;" ::: "memory");

        const uint32_t sb = dbase + (s % NBUF) * STAGEB;
#pragma unroll
        for (int ks = 0; ks < 4; ks++) {
            const uint32_t kc = (uint32_t)(ks * 32 + fcol) ^ fxor;
            uint32_t ahb[2][4], alb[2][4], bhb[NG][4], blb[NG][4];
#pragma unroll
            for (int mi = 0; mi < 2; mi++) {
                uint32_t ra = sb + (wm + mi * 16 + frow) * 128 + kc;
                LDSM_X4(ahb[mi][0], ahb[mi][1], ahb[mi][2], ahb[mi][3], ra);
                LDSM_X4(alb[mi][0], alb[mi][1], alb[mi][2], alb[mi][3], ra + OFF_AL);
            }
#pragma unroll
            for (int ni = 0; ni < NG; ni++) {
                uint32_t rb = sb + OFF_BH + (wn + ni * 16 + frow) * 128 + kc;
                LDSM_X4(bhb[ni][0], bhb[ni][1], bhb[ni][2], bhb[ni][3], rb);
                LDSM_X4(blb[ni][0], blb[ni][1], blb[ni][2], blb[ni][3], rb + BHL);
            }
#pragma unroll
            for (int mi = 0; mi < 2; mi++)
#pragma unroll
                for (int nj = 0; nj < NJ; nj++)
                    MMA_BF16(acc[mi][nj], ahb[mi], bhb[nj >> 1][nj & 1], bhb[nj >> 1][(nj & 1) + 2]);
#pragma unroll
            for (int mi = 0; mi < 2; mi++)
#pragma unroll
                for (int nj = 0; nj < NJ; nj++)
                    MMA_BF16(acc[mi][nj], ahb[mi], blb[nj >> 1][nj & 1], blb[nj >> 1][(nj & 1) + 2]);
#pragma unroll
            for (int mi = 0; mi < 2; mi++)
#pragma unroll
                for (int nj = 0; nj < NJ; nj++)
                    MMA_BF16(acc[mi][nj], alb[mi], bhb[nj >> 1][nj & 1], bhb[nj >> 1][(nj & 1) + 2]);
        }
    }

    // ---------------- epilogue ------------------------------------------------
    const int gr = lane >> 2, gc = lane & 3;
    const bool second = DUAL && (m0 >= Dm);
#pragma unroll
    for (int mi = 0; mi < 2; mi++) {
#pragma unroll
        for (int half = 0; half < 2; half++) {
            const int m = m0 + wm + mi * 16 + gr + half * 8;
            const int mrow = second ? (m - Dm) : m;
            float bm = 0.0f;
            if ((EPI == 1 || EPI == 2) && BIASROW) bm = bias[m];
#pragma unroll
            for (int nj = 0; nj < NJ; nj++) {
                const int n = n0 + wn + nj * 8 + 2 * gc;
                float v0 = acc[mi][nj][half * 2 + 0];
                float v1 = acc[mi][nj][half * 2 + 1];
                size_t idx = (size_t)mrow * Nn + n;
                if (WQ) {
                    // q = sigmoid(-v) = exp(-softplus(v))
                    float t0 = expf(-fabsf(v0)), t1 = expf(-fabsf(v1));
                    float q0 = (v0 >= 0.0f) ? t0 / (1.0f + t0) : 1.0f / (1.0f + t0);
                    float q1 = (v1 >= 0.0f) ? t1 / (1.0f + t1) : 1.0f / (1.0f + t1);
                    *(float2*)&Cq[idx] = make_float2(q0, q1);
                }
                if (EPI == 1 || EPI == 2) {
                    if (BIASROW) { v0 += bm; v1 += bm; }
                    else         { v0 += bias[n]; v1 += bias[n + 1]; }
                }
                if (EPI == 2 || (DUAL && second)) {
                    v0 *= sigmoidf_(v0); v1 *= sigmoidf_(v1);
                }
                if (EPI == 3) {
                    v0 = fmaxf(v0, 0.0f) + log1pf(expf(-fabsf(v0)));
                    v1 = fmaxf(v1, 0.0f) + log1pf(expf(-fabsf(v1)));
                }
                const bool wf = WF32 && !(DUAL && second);
                const bool ws = (WSPLIT && !DUAL) || (DUAL && second);
                if (wf) *(float2*)&Cf[idx] = make_float2(v0, v1);
                if (ws) {
                    bf16 h0 = __float2bfloat16(v0);
                    bf16 h1 = __float2bfloat16(v1);
                    __nv_bfloat162 hh; hh.x = h0; hh.y = h1;
                    __nv_bfloat162 ll;
                    ll.x = __float2bfloat16(v0 - __bfloat162float(h0));
                    ll.y = __float2bfloat16(v1 - __bfloat162float(h1));
                    *(__nv_bfloat162*)&Chi[idx] = hh;
                    *(__nv_bfloat162*)&Clo[idx] = ll;
                }
            }
        }
    }
}

// ---------------- B/C projections: [L,D] @ [D,16] ---------------------------
__global__ void __launch_bounds__(256) bc_kernel(const float* __restrict__ Xc,
                                                 const float* __restrict__ WB,
                                                 const float* __restrict__ WC,
                                                 float* __restrict__ Bo,
                                                 float* __restrict__ Co) {
    __shared__ float row[Dm];
    const int l = blockIdx.x;
    for (int k = threadIdx.x; k < Dm; k += 256) row[k] = Xc[(size_t)l * Dm + k];
    __syncthreads();
    const int part = threadIdx.x & 7;
    const int out = threadIdx.x >> 3;   // 0..31
    const int n = out & 15;
    const float* W = (out < 16) ? WB : WC;
    float s = 0.0f;
    for (int k = part; k < Dm; k += 8) s = fmaf(row[k], W[k * Ns + n], s);
#pragma unroll
    for (int off = 4; off; off >>= 1) s += __shfl_down_sync(0xffffffffu, s, off, 8);
    if (part == 0) {
        if (out < 16) Bo[l * Ns + n] = s;
        else          Co[l * Ns + n] = s;
    }
}

// ---------------- selective scan v2 (q-power, no MUFU) -----------------------
// Thread layout: block 128 = 32 d x 4 n-groups (4 n each). Grid 32.
// e[n] = exp(delta*A[d,n]) = q^{c_n}, q = exp(-delta) (from delta epilogue),
// c_n = exp(A_log[d,n]). Fast path when c_n == 4*ng+j+1 (consecutive ints).
__global__ void __launch_bounds__(128) scan_kernel(const float* __restrict__ delta,
                                                   const float* __restrict__ Q,
                                                   const float* __restrict__ Xc,
                                                   const float* __restrict__ Bm,
                                                   const float* __restrict__ Cm,
                                                   const float* __restrict__ Alog,
                                                   bf16* __restrict__ Yhi,
                                                   bf16* __restrict__ Ylo) {
    const int tid = threadIdx.x;
    const int dl = tid >> 2;                 // 0..31
    const int ng = tid & 3;                  // n-group
    const int d = blockIdx.x * 32 + dl;

    float c[4];
    bool fast = true;
#pragma unroll
    for (int j = 0; j < 4; j++) {
        c[j] = expf(Alog[d * Ns + 4 * ng + j]);
        fast &= fabsf(c[j] - (float)(4 * ng + j + 1)) < 1e-3f;
    }
    fast = __all_sync(0xffffffffu, fast);

    float h[4] = {0.0f, 0.0f, 0.0f, 0.0f};
    const float4* Bv4 = (const float4*)(Bm + 4 * ng);
    const float4* Cv4 = (const float4*)(Cm + 4 * ng);

#pragma unroll 4
    for (int l = 0; l < Dm; l++) {
        const size_t ix = (size_t)l * Dm + d;
        float de = delta[ix];
        float q  = Q[ix];
        float xv = Xc[ix];
        float4 Bv = Bv4[l * 4];
        float4 Cv = Cv4[l * 4];
        float e[4];
        if (fast) {
            float q2 = q * q, q4 = q2 * q2;
            float base = (ng == 0) ? 1.0f
                       : (ng == 1) ? q4
                       : (ng == 2) ? q4 * q4
                                   : q4 * q4 * q4;
            e[0] = base * q;
            e[1] = e[0] * q;
            e[2] = e[1] * q;
            e[3] = e[2] * q;
        } else {
#pragma unroll
            for (int j = 0; j < 4; j++) e[j] = exp_fma(-de * c[j]);
        }
        float u = de * xv;
        h[0] = fmaf(e[0], h[0], u * Bv.x);
        h[1] = fmaf(e[1], h[1], u * Bv.y);
        h[2] = fmaf(e[2], h[2], u * Bv.z);
        h[3] = fmaf(e[3], h[3], u * Bv.w);
        float p = h[0] * Cv.x + h[1] * Cv.y + h[2] * Cv.z + h[3] * Cv.w;
        p += __shfl_down_sync(0xffffffffu, p, 2, 4);
        p += __shfl_down_sync(0xffffffffu, p, 1, 4);
        if (ng == 0) {
            bf16 hh = __float2bfloat16(p);
            Yhi[ix] = hh;
            Ylo[ix] = __float2bfloat16(p - __bfloat162float(hh));
        }
    }
}

// ---------------- launch ------------------------------------------------------
extern "C" void kernel_launch(void* const* d_in, const int* in_sizes, int n_in,
                              void* d_out, int out_size) {
    const float* x    = (const float*)d_in[0];
    const float* Wp   = (const float*)d_in[1];
    const float* bp   = (const float*)d_in[2];
    const float* cw   = (const float*)d_in[3];
    const float* cb   = (const float*)d_in[4];
    const float* Alog = (const float*)d_in[5];
    const float* Wd   = (const float*)d_in[6];
    const float* WB   = (const float*)d_in[7];
    const float* WC   = (const float*)d_in[8];
    float* out = (float*)d_out;

    bf16 *xhi, *xlo, *Wphi, *Wplo, *cwhi, *cwlo, *WdThi, *WdTlo;
    bf16 *xghi, *xglo, *cBhi, *cBlo, *xchi, *xclo, *yhi, *ylo, *thi, *tlo;
    float *p0, *xc, *del, *qm, *Bm, *Cm;
    cudaGetSymbolAddress((void**)&xhi, g_xhi);   cudaGetSymbolAddress((void**)&xlo, g_xlo);
    cudaGetSymbolAddress((void**)&Wphi, g_Wphi); cudaGetSymbolAddress((void**)&Wplo, g_Wplo);
    cudaGetSymbolAddress((void**)&cwhi, g_cwhi); cudaGetSymbolAddress((void**)&cwlo, g_cwlo);
    cudaGetSymbolAddress((void**)&WdThi, g_WdThi); cudaGetSymbolAddress((void**)&WdTlo, g_WdTlo);
    cudaGetSymbolAddress((void**)&xghi, g_xghi); cudaGetSymbolAddress((void**)&xglo, g_xglo);
    cudaGetSymbolAddress((void**)&cBhi, g_cBhi); cudaGetSymbolAddress((void**)&cBlo, g_cBlo);
    cudaGetSymbolAddress((void**)&xchi, g_xchi); cudaGetSymbolAddress((void**)&xclo, g_xclo);
    cudaGetSymbolAddress((void**)&yhi, g_yhi);   cudaGetSymbolAddress((void**)&ylo, g_ylo);
    cudaGetSymbolAddress((void**)&thi, g_thi);   cudaGetSymbolAddress((void**)&tlo, g_tlo);
    cudaGetSymbolAddress((void**)&p0, g_p0);
    cudaGetSymbolAddress((void**)&xc, g_xc);
    cudaGetSymbolAddress((void**)&del, g_delta);
    cudaGetSymbolAddress((void**)&qm, g_q);
    cudaGetSymbolAddress((void**)&Bm, g_Bm);
    cudaGetSymbolAddress((void**)&Cm, g_Cm);

    const int SMEM128 = 3 * 65536;  // TM=128,TN=128: 3 buffers
    const int SMEM64  = 4 * 49152;  // TM=64, TN=128: 4 buffers
    cudaFuncSetAttribute(gemm_mma<128, 128, 1, false, true,  true,  true,  false>, cudaFuncAttributeMaxDynamicSharedMemorySize, SMEM128);
    cudaFuncSetAttribute(gemm_mma<64,  128, 2, true,  true,  true,  false, false>, cudaFuncAttributeMaxDynamicSharedMemorySize, SMEM64);
    cudaFuncSetAttribute(gemm_mma<64,  128, 3, false, true,  false, false, true>,  cudaFuncAttributeMaxDynamicSharedMemorySize, SMEM64);
    cudaFuncSetAttribute(gemm_mma<64,  128, 0, false, false, true,  false, false>, cudaFuncAttributeMaxDynamicSharedMemorySize, SMEM64);
    cudaFuncSetAttribute(gemm_mma<64,  128, 1, false, true,  false, false, false>, cudaFuncAttributeMaxDynamicSharedMemorySize, SMEM64);

    // #1..#3: splits needed by the proj GEMM
    split_k<<<(2 * Dm * Dm) / 2048, 256>>>(x, xhi, xlo, 2 * Dm * Dm);
    split_k<<<(Dm * Dm) / 2048, 256>>>(Wp, Wphi, Wplo, Dm * Dm);
    transpose_split_k<<<dim3(32, 32), dim3(32, 8)>>>(Wd, WdThi, WdTlo);

    // #4 (ncu slot): fused input projections, M=2048, 128x128, grid 128 = 1 wave
    gemm_mma<128, 128, 1, false, true, true, true, false><<<dim3(8, 16), 512, SMEM128>>>(
        xhi, xlo, Wphi, Wplo, bp, p0, xghi, xglo, nullptr, Dm, Dm);

    // conv operand prep
    split_k<<<(Dm * KC) / 2048, 256>>>(cw, cwhi, cwlo, Dm * KC);
    conv_b_build<<<dim3(32, 32), 256>>>(p0, cBhi, cBlo);

    // conv as GEMM (K = 3072), 64x128 tiles -> grid 128
    gemm_mma<64, 128, 2, true, true, true, false, false><<<dim3(8, 16), 512, SMEM64>>>(
        cwhi, cwlo, cBhi, cBlo, cb, xc, xchi, xclo, nullptr, Dm, KC);

    // delta = softplus(xc @ W_delta); also q = exp(-delta)
    gemm_mma<64, 128, 3, false, true, false, false, true><<<dim3(8, 16), 512, SMEM64>>>(
        xchi, xclo, WdThi, WdTlo, nullptr, del, nullptr, nullptr, qm, Dm, Dm);

    // B, C projections + scan
    bc_kernel<<<Dm, 256>>>(xc, WB, WC, Bm, Cm);
    scan_kernel<<<32, 128>>>(del, qm, xc, Bm, Cm, Alog, yhi, ylo);

    // t = y @ xg^T
    gemm_mma<64, 128, 0, false, false, true, false, false><<<dim3(8, 16), 512, SMEM64>>>(
        yhi, ylo, xghi, xglo, nullptr, nullptr, thi, tlo, nullptr, Dm, Dm);

    // out = t @ Wp^T + b
    gemm_mma<64, 128, 1, false, true, false, false, false><<<dim3(8, 16), 512, SMEM64>>>(
        thi, tlo, Wphi, Wplo, bp, out, nullptr, nullptr, nullptr, Dm, Dm);
}

// round 8
// speedup vs baseline: 1.0691x; 1.0691x over previous
#include <cuda_runtime.h>
#include <cuda_bf16.h>
#include <math.h>
#include <stdint.h>

constexpr int Dm = 1024;   // dim == seq len L
constexpr int Ns = 16;     // SSM state size
constexpr int KC = 3 * Dm; // conv GEMM K = 3072

typedef __nv_bfloat16 bf16;

// ---------------- scratch (static device globals: allocation-free) ----------
__device__ bf16 g_xhi[2 * Dm * Dm], g_xlo[2 * Dm * Dm];
__device__ bf16 g_Wphi[Dm * Dm],   g_Wplo[Dm * Dm];
__device__ bf16 g_cwhi[Dm * KC],   g_cwlo[Dm * KC];
__device__ bf16 g_WdThi[Dm * Dm],  g_WdTlo[Dm * Dm];
__device__ float g_p0[Dm * Dm];
__device__ bf16 g_xghi[Dm * Dm],   g_xglo[Dm * Dm];
__device__ bf16 g_cBhi[Dm * KC],   g_cBlo[Dm * KC];
__device__ float g_xc[Dm * Dm];
__device__ bf16 g_xchi[Dm * Dm],   g_xclo[Dm * Dm];
__device__ float g_delta[Dm * Dm];
__device__ float g_q[Dm * Dm];     // exp(-delta) = sigmoid(-raw), from delta epilogue
__device__ float g_Bm[Dm * Ns], g_Cm[Dm * Ns];
__device__ bf16 g_yhi[Dm * Dm],    g_ylo[Dm * Dm];
__device__ bf16 g_thi[Dm * Dm],    g_tlo[Dm * Dm];

__device__ __forceinline__ float sigmoidf_(float x) {
    return 1.0f / (1.0f + expf(-x));
}

__device__ __forceinline__ uint32_t smem_u32(const void* p) {
    uint32_t a;
    asm("{ .reg .u64 t; cvta.to.shared.u64 t, %1; cvt.u32.u64 %0, t; }" : "=r"(a) : "l"(p));
    return a;
}

#define SWZ(x) ((x) ^ (((x) >> 3) & 0x70))

__device__ __forceinline__ void cpa16(uint32_t dst, const void* src) {
    asm volatile("cp.async.cg.shared.global [%0], [%1], 16;" :: "r"(dst), "l"(src));
}

#define MMA_BF16(c, a, b0, b1)                                                   \
    asm volatile(                                                                \
        "mma.sync.aligned.m16n8k16.row.col.f32.bf16.bf16.f32 "                   \
        "{%0,%1,%2,%3},{%4,%5,%6,%7},{%8,%9},{%0,%1,%2,%3};"                     \
        : "+f"(c[0]), "+f"(c[1]), "+f"(c[2]), "+f"(c[3])                         \
        : "r"(a[0]), "r"(a[1]), "r"(a[2]), "r"(a[3]), "r"(b0), "r"(b1))

#define LDSM_X4(r0, r1, r2, r3, addr)                                            \
    asm volatile("ldmatrix.sync.aligned.m8n8.x4.shared.b16 {%0,%1,%2,%3}, [%4];" \
        : "=r"(r0), "=r"(r1), "=r"(r2), "=r"(r3) : "r"(addr))

// FMA-only exp (no MUFU)
__device__ __forceinline__ float exp_fma(float t) {
    float z = t * 1.44269504f;
    float r = rintf(z);
    r = fmaxf(r, -126.0f);
    float f = z - r;
    float p = 1.33335581e-3f;
    p = fmaf(p, f, 9.61812910e-3f);
    p = fmaf(p, f, 5.55041086e-2f);
    p = fmaf(p, f, 2.40226507e-1f);
    p = fmaf(p, f, 6.93147182e-1f);
    p = fmaf(p, f, 1.0f);
    return p * __int_as_float(((int)r + 127) << 23);
}

// ---------------- fp32 -> (hi,lo) bf16 split (vectorized 16B stores) --------
__global__ void __launch_bounds__(256) split_k(const float* __restrict__ in,
                                               bf16* __restrict__ hi,
                                               bf16* __restrict__ lo, int n) {
    int i = (blockIdx.x * 256 + threadIdx.x) * 8;
    if (i >= n) return;
    float4 v0 = *(const float4*)(in + i);
    float4 v1 = *(const float4*)(in + i + 4);
    float vv[8] = {v0.x, v0.y, v0.z, v0.w, v1.x, v1.y, v1.z, v1.w};
    __nv_bfloat162 hb[4], lb[4];
#pragma unroll
    for (int j = 0; j < 4; j++) {
        bf16 h0 = __float2bfloat16(vv[2 * j]);
        bf16 h1 = __float2bfloat16(vv[2 * j + 1]);
        hb[j].x = h0; hb[j].y = h1;
        lb[j].x = __float2bfloat16(vv[2 * j] - __bfloat162float(h0));
        lb[j].y = __float2bfloat16(vv[2 * j + 1] - __bfloat162float(h1));
    }
    *(int4*)(hi + i) = *(int4*)hb;
    *(int4*)(lo + i) = *(int4*)lb;
}

// ---------------- transpose + split (for W_delta) ---------------------------
__global__ void __launch_bounds__(256) transpose_split_k(const float* __restrict__ In,
                                                         bf16* __restrict__ hi,
                                                         bf16* __restrict__ lo) {
    __shared__ float t[32][33];
    int x0 = blockIdx.x * 32, y0 = blockIdx.y * 32;
    int tx = threadIdx.x;
    for (int j = threadIdx.y; j < 32; j += 8)
        t[j][tx] = In[(y0 + j) * Dm + x0 + tx];
    __syncthreads();
    for (int j = threadIdx.y; j < 32; j += 8) {
        float v = t[tx][j];
        bf16 h = __float2bfloat16(v);
        size_t idx = (size_t)(x0 + j) * Dm + y0 + tx;
        hi[idx] = h;
        lo[idx] = __float2bfloat16(v - __bfloat162float(h));
    }
}

// ---------------- build conv B matrix: B[d, i*3+kk] = p0[i, d-1+kk] ----------
__global__ void __launch_bounds__(256) conv_b_build(const float* __restrict__ P0,
                                                    bf16* __restrict__ hi,
                                                    bf16* __restrict__ lo) {
    __shared__ float Xs[32][35];
    int d0 = blockIdx.x * 32, i0 = blockIdx.y * 32;
    int tid = threadIdx.x;
    for (int idx = tid; idx < 32 * 34; idx += 256) {
        int r = idx / 34, c = idx % 34;
        int gd = d0 - 1 + c;
        Xs[r][c] = (gd >= 0 && gd < Dm) ? P0[(size_t)(i0 + r) * Dm + gd] : 0.0f;
    }
    __syncthreads();
    int i = tid & 31;
    for (int dl = tid >> 5; dl < 32; dl += 8) {
        size_t base = (size_t)(d0 + dl) * KC + (size_t)(i0 + i) * 3;
#pragma unroll
        for (int kk = 0; kk < 3; kk++) {
            float x = Xs[i][dl + kk];
            bf16 h = __float2bfloat16(x);
            hi[base + kk] = h;
            lo[base + kk] = __float2bfloat16(x - __bfloat162float(h));
        }
    }
}

// ---------------- bf16-split HMMA GEMM, deep cp.async pipeline ---------------
// C[m,n] = sum_k A[m,k]*B[n,k]; A=Ah+Al, B=Bh+Bl; C ~= Ah*Bh + Ah*Bl + Al*Bh.
// NT threads, CTA tile TM x TN, K-block 64, NBUF buffers, 1 barrier/stage.
// Warp layout: (TM/32) x rest; warp tile 32 x WN (=32 for all configs used).
template <int NT, int TM, int TN, int EPI, bool BIASROW, bool WF32, bool WSPLIT,
          bool DUAL, bool WQ>
__global__ void __launch_bounds__(NT, 1)
gemm_mma(const bf16* __restrict__ Ah, const bf16* __restrict__ Al,
         const bf16* __restrict__ Bh, const bf16* __restrict__ Bl,
         const float* __restrict__ bias,
         float* __restrict__ Cf, bf16* __restrict__ Chi, bf16* __restrict__ Clo,
         float* __restrict__ Cq,
         int Nn, int K)
{
    constexpr int OFF_AL = TM * 128;
    constexpr int OFF_BH = TM * 256;
    constexpr int BHL = TN * 128;
    constexpr int STAGEB = (TM + TN) * 256;
    constexpr int NBUF = (STAGEB >= 65536) ? 3 : 4;
    constexpr int DEPTH = NBUF - 1;
    constexpr int WARPS_M = TM / 32;
    constexpr int NWARP = NT / 32;
    constexpr int WN = TN / (NWARP / WARPS_M);
    constexpr int NG = WN / 16;
    constexpr int NJ = WN / 8;

    extern __shared__ __align__(1024) char dyns[];
    const int tid = threadIdx.x;
    const int lane = tid & 31, warp = tid >> 5;
    const int m0 = blockIdx.y * TM, n0 = blockIdx.x * TN;
    const uint32_t dbase = smem_u32(dyns);
    const int S = K >> 6;

    float acc[2][NJ][4];
#pragma unroll
    for (int a = 0; a < 2; a++)
#pragma unroll
        for (int b = 0; b < NJ; b++)
#pragma unroll
            for (int c = 0; c < 4; c++) acc[a][b][c] = 0.0f;

    auto load_stage = [&](int s) {
        const uint32_t sb = dbase + (s % NBUF) * STAGEB;
        const int k0 = s << 6;
#pragma unroll
        for (int i = 0; i < TM * 8 / NT; i++) {
            int q = tid + i * NT;
            int r = q >> 3, c = q & 7;
            uint32_t so = SWZ((uint32_t)(r * 128 + c * 16));
            size_t ga = (size_t)(m0 + r) * K + k0 + c * 8;
            cpa16(sb + so, Ah + ga);
            cpa16(sb + OFF_AL + so, Al + ga);
        }
#pragma unroll
        for (int i = 0; i < TN * 8 / NT; i++) {
            int q = tid + i * NT;
            int r = q >> 3, c = q & 7;
            uint32_t so = SWZ((uint32_t)(r * 128 + c * 16));
            size_t gb = (size_t)(n0 + r) * K + k0 + c * 8;
            cpa16(sb + OFF_BH + so, Bh + gb);
            cpa16(sb + OFF_BH + BHL + so, Bl + gb);
        }
        asm volatile("cp.async.commit_group;" ::: "memory");
    };

#pragma unroll
    for (int s = 0; s < DEPTH; s++) load_stage(s);

    const int wm = (warp % WARPS_M) * 32, wn = (warp / WARPS_M) * WN;
    const uint32_t frow = (lane & 7) + ((lane >> 3) & 1) * 8;
    const uint32_t fxor = (frow & 7) << 4;
    const uint32_t fcol = (lane >> 4) << 4;

    for (int s = 0; s < S; s++) {
        asm volatile("cp.async.wait_group %0;" :: "n"(DEPTH - 1) : "memory");
        __syncthreads();
        if (s + DEPTH < S) load_stage(s + DEPTH);
        else asm volatile("cp.async.commit_group;" ::: "memory");

        const uint32_t sb = dbase + (s % NBUF) * STAGEB;
#pragma unroll
        for (int ks = 0; ks < 4; ks++) {
            const uint32_t kc = (uint32_t)(ks * 32 + fcol) ^ fxor;
            uint32_t ahb[2][4], alb[2][4], bhb[NG][4], blb[NG][4];
#pragma unroll
            for (int mi = 0; mi < 2; mi++) {
                uint32_t ra = sb + (wm + mi * 16 + frow) * 128 + kc;
                LDSM_X4(ahb[mi][0], ahb[mi][1], ahb[mi][2], ahb[mi][3], ra);
                LDSM_X4(alb[mi][0], alb[mi][1], alb[mi][2], alb[mi][3], ra + OFF_AL);
            }
#pragma unroll
            for (int ni = 0; ni < NG; ni++) {
                uint32_t rb = sb + OFF_BH + (wn + ni * 16 + frow) * 128 + kc;
                LDSM_X4(bhb[ni][0], bhb[ni][1], bhb[ni][2], bhb[ni][3], rb);
                LDSM_X4(blb[ni][0], blb[ni][1], blb[ni][2], blb[ni][3], rb + BHL);
            }
#pragma unroll
            for (int mi = 0; mi < 2; mi++)
#pragma unroll
                for (int nj = 0; nj < NJ; nj++)
                    MMA_BF16(acc[mi][nj], ahb[mi], bhb[nj >> 1][nj & 1], bhb[nj >> 1][(nj & 1) + 2]);
#pragma unroll
            for (int mi = 0; mi < 2; mi++)
#pragma unroll
                for (int nj = 0; nj < NJ; nj++)
                    MMA_BF16(acc[mi][nj], ahb[mi], blb[nj >> 1][nj & 1], blb[nj >> 1][(nj & 1) + 2]);
#pragma unroll
            for (int mi = 0; mi < 2; mi++)
#pragma unroll
                for (int nj = 0; nj < NJ; nj++)
                    MMA_BF16(acc[mi][nj], alb[mi], bhb[nj >> 1][nj & 1], bhb[nj >> 1][(nj & 1) + 2]);
        }
    }

    // ---------------- epilogue ------------------------------------------------
    const int gr = lane >> 2, gc = lane & 3;
    const bool second = DUAL && (m0 >= Dm);
#pragma unroll
    for (int mi = 0; mi < 2; mi++) {
#pragma unroll
        for (int half = 0; half < 2; half++) {
            const int m = m0 + wm + mi * 16 + gr + half * 8;
            const int mrow = second ? (m - Dm) : m;
            float bm = 0.0f;
            if ((EPI == 1 || EPI == 2) && BIASROW) bm = bias[m];
#pragma unroll
            for (int nj = 0; nj < NJ; nj++) {
                const int n = n0 + wn + nj * 8 + 2 * gc;
                float v0 = acc[mi][nj][half * 2 + 0];
                float v1 = acc[mi][nj][half * 2 + 1];
                size_t idx = (size_t)mrow * Nn + n;
                if (WQ) {
                    // q = sigmoid(-v) = exp(-softplus(v))
                    float t0 = expf(-fabsf(v0)), t1 = expf(-fabsf(v1));
                    float q0 = (v0 >= 0.0f) ? t0 / (1.0f + t0) : 1.0f / (1.0f + t0);
                    float q1 = (v1 >= 0.0f) ? t1 / (1.0f + t1) : 1.0f / (1.0f + t1);
                    *(float2*)&Cq[idx] = make_float2(q0, q1);
                }
                if (EPI == 1 || EPI == 2) {
                    if (BIASROW) { v0 += bm; v1 += bm; }
                    else         { v0 += bias[n]; v1 += bias[n + 1]; }
                }
                if (EPI == 2 || (DUAL && second)) {
                    v0 *= sigmoidf_(v0); v1 *= sigmoidf_(v1);
                }
                if (EPI == 3) {
                    v0 = fmaxf(v0, 0.0f) + log1pf(expf(-fabsf(v0)));
                    v1 = fmaxf(v1, 0.0f) + log1pf(expf(-fabsf(v1)));
                }
                const bool wf = WF32 && !(DUAL && second);
                const bool ws = (WSPLIT && !DUAL) || (DUAL && second);
                if (wf) *(float2*)&Cf[idx] = make_float2(v0, v1);
                if (ws) {
                    bf16 h0 = __float2bfloat16(v0);
                    bf16 h1 = __float2bfloat16(v1);
                    __nv_bfloat162 hh; hh.x = h0; hh.y = h1;
                    __nv_bfloat162 ll;
                    ll.x = __float2bfloat16(v0 - __bfloat162float(h0));
                    ll.y = __float2bfloat16(v1 - __bfloat162float(h1));
                    *(__nv_bfloat162*)&Chi[idx] = hh;
                    *(__nv_bfloat162*)&Clo[idx] = ll;
                }
            }
        }
    }
}

// ---------------- B/C projections: [L,D] @ [D,16] ---------------------------
__global__ void __launch_bounds__(256) bc_kernel(const float* __restrict__ Xc,
                                                 const float* __restrict__ WB,
                                                 const float* __restrict__ WC,
                                                 float* __restrict__ Bo,
                                                 float* __restrict__ Co) {
    __shared__ float row[Dm];
    const int l = blockIdx.x;
    for (int k = threadIdx.x; k < Dm; k += 256) row[k] = Xc[(size_t)l * Dm + k];
    __syncthreads();
    const int part = threadIdx.x & 7;
    const int out = threadIdx.x >> 3;   // 0..31
    const int n = out & 15;
    const float* W = (out < 16) ? WB : WC;
    float s = 0.0f;
    for (int k = part; k < Dm; k += 8) s = fmaf(row[k], W[k * Ns + n], s);
#pragma unroll
    for (int off = 4; off; off >>= 1) s += __shfl_down_sync(0xffffffffu, s, off, 8);
    if (part == 0) {
        if (out < 16) Bo[l * Ns + n] = s;
        else          Co[l * Ns + n] = s;
    }
}

// ---------------- selective scan v3: full-chip, no MUFU ----------------------
// Thread per (d,n): grid 128 x 128 threads (8 d x 16 n per block).
// e = exp(delta*A[d,n]) = q^(n+1) (q = exp(-delta)); exp_fma fallback.
__global__ void __launch_bounds__(128) scan_kernel(const float* __restrict__ delta,
                                                   const float* __restrict__ Q,
                                                   const float* __restrict__ Xc,
                                                   const float* __restrict__ Bm,
                                                   const float* __restrict__ Cm,
                                                   const float* __restrict__ Alog,
                                                   bf16* __restrict__ Yhi,
                                                   bf16* __restrict__ Ylo) {
    const int n = threadIdx.x & 15;
    const int d = blockIdx.x * 8 + (threadIdx.x >> 4);
    const float c = expf(Alog[d * Ns + n]);
    const int p = n + 1;
    bool fast = fabsf(c - (float)p) < 1e-3f;
    fast = __all_sync(0xffffffffu, fast);
    const bool b1 = (p & 1), b2 = (p & 2), b4 = (p & 4), b8 = (p & 8), b16 = (p & 16);

    float h = 0.0f;
    for (int l = 0; l < Dm; l++) {
        const size_t ix = (size_t)l * Dm + d;
        float de = delta[ix];
        float xv = Xc[ix];
        float bv = Bm[l * Ns + n];
        float cv = Cm[l * Ns + n];
        float e;
        if (fast) {
            float q = Q[ix];
            float q2 = q * q, q4 = q2 * q2, q8 = q4 * q4;
            e = 1.0f;
            if (b1) e *= q;
            if (b2) e *= q2;
            if (b4) e *= q4;
            if (b8) e *= q8;
            if (b16) e = q8 * q8;
        } else {
            e = exp_fma(-de * c);
        }
        h = fmaf(e, h, de * xv * bv);
        float pr = h * cv;
#pragma unroll
        for (int off = 8; off; off >>= 1)
            pr += __shfl_down_sync(0xffffffffu, pr, off, 16);
        if (n == 0) {
            bf16 hh = __float2bfloat16(pr);
            Yhi[ix] = hh;
            Ylo[ix] = __float2bfloat16(pr - __bfloat162float(hh));
        }
    }
}

// ---------------- launch ------------------------------------------------------
extern "C" void kernel_launch(void* const* d_in, const int* in_sizes, int n_in,
                              void* d_out, int out_size) {
    const float* x    = (const float*)d_in[0];
    const float* Wp   = (const float*)d_in[1];
    const float* bp   = (const float*)d_in[2];
    const float* cw   = (const float*)d_in[3];
    const float* cb   = (const float*)d_in[4];
    const float* Alog = (const float*)d_in[5];
    const float* Wd   = (const float*)d_in[6];
    const float* WB   = (const float*)d_in[7];
    const float* WC   = (const float*)d_in[8];
    float* out = (float*)d_out;

    bf16 *xhi, *xlo, *Wphi, *Wplo, *cwhi, *cwlo, *WdThi, *WdTlo;
    bf16 *xghi, *xglo, *cBhi, *cBlo, *xchi, *xclo, *yhi, *ylo, *thi, *tlo;
    float *p0, *xc, *del, *qm, *Bm, *Cm;
    cudaGetSymbolAddress((void**)&xhi, g_xhi);   cudaGetSymbolAddress((void**)&xlo, g_xlo);
    cudaGetSymbolAddress((void**)&Wphi, g_Wphi); cudaGetSymbolAddress((void**)&Wplo, g_Wplo);
    cudaGetSymbolAddress((void**)&cwhi, g_cwhi); cudaGetSymbolAddress((void**)&cwlo, g_cwlo);
    cudaGetSymbolAddress((void**)&WdThi, g_WdThi); cudaGetSymbolAddress((void**)&WdTlo, g_WdTlo);
    cudaGetSymbolAddress((void**)&xghi, g_xghi); cudaGetSymbolAddress((void**)&xglo, g_xglo);
    cudaGetSymbolAddress((void**)&cBhi, g_cBhi); cudaGetSymbolAddress((void**)&cBlo, g_cBlo);
    cudaGetSymbolAddress((void**)&xchi, g_xchi); cudaGetSymbolAddress((void**)&xclo, g_xclo);
    cudaGetSymbolAddress((void**)&yhi, g_yhi);   cudaGetSymbolAddress((void**)&ylo, g_ylo);
    cudaGetSymbolAddress((void**)&thi, g_thi);   cudaGetSymbolAddress((void**)&tlo, g_tlo);
    cudaGetSymbolAddress((void**)&p0, g_p0);
    cudaGetSymbolAddress((void**)&xc, g_xc);
    cudaGetSymbolAddress((void**)&del, g_delta);
    cudaGetSymbolAddress((void**)&qm, g_q);
    cudaGetSymbolAddress((void**)&Bm, g_Bm);
    cudaGetSymbolAddress((void**)&Cm, g_Cm);

    const int SMEM128 = 3 * 65536;  // proj: TM=128,TN=128, 3 buffers
    const int SMEM64  = 4 * 49152;  // squares: TM=128,TN=64, 4 buffers
    cudaFuncSetAttribute(gemm_mma<512, 128, 128, 1, false, true,  true,  true,  false>, cudaFuncAttributeMaxDynamicSharedMemorySize, SMEM128);
    cudaFuncSetAttribute(gemm_mma<256, 128, 64,  2, true,  true,  true,  false, false>, cudaFuncAttributeMaxDynamicSharedMemorySize, SMEM64);
    cudaFuncSetAttribute(gemm_mma<256, 128, 64,  3, false, true,  false, false, true>,  cudaFuncAttributeMaxDynamicSharedMemorySize, SMEM64);
    cudaFuncSetAttribute(gemm_mma<256, 128, 64,  0, false, false, true,  false, false>, cudaFuncAttributeMaxDynamicSharedMemorySize, SMEM64);
    cudaFuncSetAttribute(gemm_mma<256, 128, 64,  1, false, true,  false, false, false>, cudaFuncAttributeMaxDynamicSharedMemorySize, SMEM64);

    // #1..#3: splits needed by the proj GEMM
    split_k<<<(2 * Dm * Dm) / 2048, 256>>>(x, xhi, xlo, 2 * Dm * Dm);
    split_k<<<(Dm * Dm) / 2048, 256>>>(Wp, Wphi, Wplo, Dm * Dm);
    transpose_split_k<<<dim3(32, 32), dim3(32, 8)>>>(Wd, WdThi, WdTlo);

    // #4 (ncu slot): fused input projections, M=2048, 128x128, 512 thr, 1 wave
    gemm_mma<512, 128, 128, 1, false, true, true, true, false><<<dim3(8, 16), 512, SMEM128>>>(
        xhi, xlo, Wphi, Wplo, bp, p0, xghi, xglo, nullptr, Dm, Dm);

    // conv operand prep
    split_k<<<(Dm * KC) / 2048, 256>>>(cw, cwhi, cwlo, Dm * KC);
    conv_b_build<<<dim3(32, 32), 256>>>(p0, cBhi, cBlo);

    // conv as GEMM (K = 3072), 128x64 tiles, 256 thr
    gemm_mma<256, 128, 64, 2, true, true, true, false, false><<<dim3(16, 8), 256, SMEM64>>>(
        cwhi, cwlo, cBhi, cBlo, cb, xc, xchi, xclo, nullptr, Dm, KC);

    // delta = softplus(xc @ W_delta); also q = exp(-delta)
    gemm_mma<256, 128, 64, 3, false, true, false, false, true><<<dim3(16, 8), 256, SMEM64>>>(
        xchi, xclo, WdThi, WdTlo, nullptr, del, nullptr, nullptr, qm, Dm, Dm);

    // B, C projections + scan
    bc_kernel<<<Dm, 256>>>(xc, WB, WC, Bm, Cm);
    scan_kernel<<<Dm / 8, 128>>>(del, qm, xc, Bm, Cm, Alog, yhi, ylo);

    // t = y @ xg^T
    gemm_mma<256, 128, 64, 0, false, false, true, false, false><<<dim3(16, 8), 256, SMEM64>>>(
        yhi, ylo, xghi, xglo, nullptr, nullptr, thi, tlo, nullptr, Dm, Dm);

    // out = t @ Wp^T + b
    gemm_mma<256, 128, 64, 1, false, true, false, false, false><<<dim3(16, 8), 256, SMEM64>>>(
        thi, tlo, Wphi, Wplo, bp, out, nullptr, nullptr, nullptr, Dm, Dm);
}

// round 9
// speedup vs baseline: 1.2311x; 1.1516x over previous
#include <cuda_runtime.h>
#include <cuda_bf16.h>
#include <math.h>
#include <stdint.h>

constexpr int Dm = 1024;   // dim == seq len L
constexpr int Ns = 16;     // SSM state size
constexpr int KC = 3 * Dm; // conv GEMM K = 3072

typedef __nv_bfloat16 bf16;

// ---------------- scratch (static device globals: allocation-free) ----------
__device__ bf16 g_xhi[2 * Dm * Dm], g_xlo[2 * Dm * Dm];
__device__ bf16 g_Wphi[Dm * Dm],   g_Wplo[Dm * Dm];
__device__ bf16 g_cwhi[Dm * KC],   g_cwlo[Dm * KC];
__device__ bf16 g_WdThi[Dm * Dm],  g_WdTlo[Dm * Dm];
__device__ float g_p0[Dm * Dm];
__device__ bf16 g_xghi[Dm * Dm],   g_xglo[Dm * Dm];
__device__ bf16 g_cBhi[Dm * KC],   g_cBlo[Dm * KC];
__device__ float g_xc[Dm * Dm];
__device__ bf16 g_xchi[Dm * Dm],   g_xclo[Dm * Dm];
__device__ float g_delta[Dm * Dm];
__device__ float g_Bm[Dm * Ns], g_Cm[Dm * Ns];
__device__ bf16 g_yhi[Dm * Dm],    g_ylo[Dm * Dm];
__device__ bf16 g_thi[Dm * Dm],    g_tlo[Dm * Dm];

__device__ __forceinline__ float sigmoidf_(float x) {
    return 1.0f / (1.0f + expf(-x));
}

__device__ __forceinline__ uint32_t smem_u32(const void* p) {
    uint32_t a;
    asm("{ .reg .u64 t; cvta.to.shared.u64 t, %1; cvt.u32.u64 %0, t; }" : "=r"(a) : "l"(p));
    return a;
}

#define SWZ(x) ((x) ^ (((x) >> 3) & 0x70))

__device__ __forceinline__ void cpa16(uint32_t dst, const void* src) {
    asm volatile("cp.async.cg.shared.global [%0], [%1], 16;" :: "r"(dst), "l"(src));
}

#define MMA_BF16(c, a, b0, b1)                                                   \
    asm volatile(                                                                \
        "mma.sync.aligned.m16n8k16.row.col.f32.bf16.bf16.f32 "                   \
        "{%0,%1,%2,%3},{%4,%5,%6,%7},{%8,%9},{%0,%1,%2,%3};"                     \
        : "+f"(c[0]), "+f"(c[1]), "+f"(c[2]), "+f"(c[3])                         \
        : "r"(a[0]), "r"(a[1]), "r"(a[2]), "r"(a[3]), "r"(b0), "r"(b1))

#define LDSM_X4(r0, r1, r2, r3, addr)                                            \
    asm volatile("ldmatrix.sync.aligned.m8n8.x4.shared.b16 {%0,%1,%2,%3}, [%4];" \
        : "=r"(r0), "=r"(r1), "=r"(r2), "=r"(r3) : "r"(addr))

// FMA-only exp for t <= 0, underflow-guarded (no MUFU)
__device__ __forceinline__ float exp_fma(float t) {
    float z = t * 1.44269504f;
    float r = rintf(z);
    float f = z - r;
    float p = 1.33335581e-3f;
    p = fmaf(p, f, 9.61812910e-3f);
    p = fmaf(p, f, 5.55041086e-2f);
    p = fmaf(p, f, 2.40226507e-1f);
    p = fmaf(p, f, 6.93147182e-1f);
    p = fmaf(p, f, 1.0f);
    int ri = (int)r;
    float sc = (ri < -126) ? 0.0f : __int_as_float((ri + 127) << 23);
    return p * sc;
}

// ---------------- fp32 -> (hi,lo) bf16 split (vectorized 16B stores) --------
__global__ void __launch_bounds__(256) split_k(const float* __restrict__ in,
                                               bf16* __restrict__ hi,
                                               bf16* __restrict__ lo, int n) {
    int i = (blockIdx.x * 256 + threadIdx.x) * 8;
    if (i >= n) return;
    float4 v0 = *(const float4*)(in + i);
    float4 v1 = *(const float4*)(in + i + 4);
    float vv[8] = {v0.x, v0.y, v0.z, v0.w, v1.x, v1.y, v1.z, v1.w};
    __nv_bfloat162 hb[4], lb[4];
#pragma unroll
    for (int j = 0; j < 4; j++) {
        bf16 h0 = __float2bfloat16(vv[2 * j]);
        bf16 h1 = __float2bfloat16(vv[2 * j + 1]);
        hb[j].x = h0; hb[j].y = h1;
        lb[j].x = __float2bfloat16(vv[2 * j] - __bfloat162float(h0));
        lb[j].y = __float2bfloat16(vv[2 * j + 1] - __bfloat162float(h1));
    }
    *(int4*)(hi + i) = *(int4*)hb;
    *(int4*)(lo + i) = *(int4*)lb;
}

// ---------------- transpose + split (for W_delta) ---------------------------
__global__ void __launch_bounds__(256) transpose_split_k(const float* __restrict__ In,
                                                         bf16* __restrict__ hi,
                                                         bf16* __restrict__ lo) {
    __shared__ float t[32][33];
    int x0 = blockIdx.x * 32, y0 = blockIdx.y * 32;
    int tx = threadIdx.x;
    for (int j = threadIdx.y; j < 32; j += 8)
        t[j][tx] = In[(y0 + j) * Dm + x0 + tx];
    __syncthreads();
    for (int j = threadIdx.y; j < 32; j += 8) {
        float v = t[tx][j];
        bf16 h = __float2bfloat16(v);
        size_t idx = (size_t)(x0 + j) * Dm + y0 + tx;
        hi[idx] = h;
        lo[idx] = __float2bfloat16(v - __bfloat162float(h));
    }
}

// ---------------- build conv B matrix: B[d, i*3+kk] = p0[i, d-1+kk] ----------
__global__ void __launch_bounds__(256) conv_b_build(const float* __restrict__ P0,
                                                    bf16* __restrict__ hi,
                                                    bf16* __restrict__ lo) {
    __shared__ float Xs[32][35];
    int d0 = blockIdx.x * 32, i0 = blockIdx.y * 32;
    int tid = threadIdx.x;
    for (int idx = tid; idx < 32 * 34; idx += 256) {
        int r = idx / 34, c = idx % 34;
        int gd = d0 - 1 + c;
        Xs[r][c] = (gd >= 0 && gd < Dm) ? P0[(size_t)(i0 + r) * Dm + gd] : 0.0f;
    }
    __syncthreads();
    int i = tid & 31;
    for (int dl = tid >> 5; dl < 32; dl += 8) {
        size_t base = (size_t)(d0 + dl) * KC + (size_t)(i0 + i) * 3;
#pragma unroll
        for (int kk = 0; kk < 3; kk++) {
            float x = Xs[i][dl + kk];
            bf16 h = __float2bfloat16(x);
            hi[base + kk] = h;
            lo[base + kk] = __float2bfloat16(x - __bfloat162float(h));
        }
    }
}

// ---------------- bf16-split HMMA GEMM, deep cp.async pipeline ---------------
// C[m,n] = sum_k A[m,k]*B[n,k]; A=Ah+Al, B=Bh+Bl; C ~= Ah*Bh + Ah*Bl + Al*Bh.
// NT threads, CTA tile TM x TN, K-block 64, NBUF buffers, 1 barrier/stage.
template <int NT, int TM, int TN, int EPI, bool BIASROW, bool WF32, bool WSPLIT,
          bool DUAL>
__global__ void __launch_bounds__(NT, 1)
gemm_mma(const bf16* __restrict__ Ah, const bf16* __restrict__ Al,
         const bf16* __restrict__ Bh, const bf16* __restrict__ Bl,
         const float* __restrict__ bias,
         float* __restrict__ Cf, bf16* __restrict__ Chi, bf16* __restrict__ Clo,
         int Nn, int K)
{
    constexpr int OFF_AL = TM * 128;
    constexpr int OFF_BH = TM * 256;
    constexpr int BHL = TN * 128;
    constexpr int STAGEB = (TM + TN) * 256;
    constexpr int NBUF = (STAGEB >= 65536) ? 3 : 4;
    constexpr int DEPTH = NBUF - 1;
    constexpr int WARPS_M = TM / 32;
    constexpr int NWARP = NT / 32;
    constexpr int WN = TN / (NWARP / WARPS_M);
    constexpr int NG = WN / 16;
    constexpr int NJ = WN / 8;

    extern __shared__ __align__(1024) char dyns[];
    const int tid = threadIdx.x;
    const int lane = tid & 31, warp = tid >> 5;
    const int m0 = blockIdx.y * TM, n0 = blockIdx.x * TN;
    const uint32_t dbase = smem_u32(dyns);
    const int S = K >> 6;

    float acc[2][NJ][4];
#pragma unroll
    for (int a = 0; a < 2; a++)
#pragma unroll
        for (int b = 0; b < NJ; b++)
#pragma unroll
            for (int c = 0; c < 4; c++) acc[a][b][c] = 0.0f;

    auto load_stage = [&](int s) {
        const uint32_t sb = dbase + (s % NBUF) * STAGEB;
        const int k0 = s << 6;
#pragma unroll
        for (int i = 0; i < TM * 8 / NT; i++) {
            int q = tid + i * NT;
            int r = q >> 3, c = q & 7;
            uint32_t so = SWZ((uint32_t)(r * 128 + c * 16));
            size_t ga = (size_t)(m0 + r) * K + k0 + c * 8;
            cpa16(sb + so, Ah + ga);
            cpa16(sb + OFF_AL + so, Al + ga);
        }
#pragma unroll
        for (int i = 0; i < TN * 8 / NT; i++) {
            int q = tid + i * NT;
            int r = q >> 3, c = q & 7;
            uint32_t so = SWZ((uint32_t)(r * 128 + c * 16));
            size_t gb = (size_t)(n0 + r) * K + k0 + c * 8;
            cpa16(sb + OFF_BH + so, Bh + gb);
            cpa16(sb + OFF_BH + BHL + so, Bl + gb);
        }
        asm volatile("cp.async.commit_group;" ::: "memory");
    };

#pragma unroll
    for (int s = 0; s < DEPTH; s++) load_stage(s);

    const int wm = (warp % WARPS_M) * 32, wn = (warp / WARPS_M) * WN;
    const uint32_t frow = (lane & 7) + ((lane >> 3) & 1) * 8;
    const uint32_t fxor = (frow & 7) << 4;
    const uint32_t fcol = (lane >> 4) << 4;

    for (int s = 0; s < S; s++) {
        asm volatile("cp.async.wait_group %0;" :: "n"(DEPTH - 1) : "memory");
        __syncthreads();
        if (s + DEPTH < S) load_stage(s + DEPTH);
        else asm volatile("cp.async.commit_group;" ::: "memory");

        const uint32_t sb = dbase + (s % NBUF) * STAGEB;
#pragma unroll
        for (int ks = 0; ks < 4; ks++) {
            const uint32_t kc = (uint32_t)(ks * 32 + fcol) ^ fxor;
            uint32_t ahb[2][4], alb[2][4], bhb[NG][4], blb[NG][4];
#pragma unroll
            for (int mi = 0; mi < 2; mi++) {
                uint32_t ra = sb + (wm + mi * 16 + frow) * 128 + kc;
                LDSM_X4(ahb[mi][0], ahb[mi][1], ahb[mi][2], ahb[mi][3], ra);
                LDSM_X4(alb[mi][0], alb[mi][1], alb[mi][2], alb[mi][3], ra + OFF_AL);
            }
#pragma unroll
            for (int ni = 0; ni < NG; ni++) {
                uint32_t rb = sb + OFF_BH + (wn + ni * 16 + frow) * 128 + kc;
                LDSM_X4(bhb[ni][0], bhb[ni][1], bhb[ni][2], bhb[ni][3], rb);
                LDSM_X4(blb[ni][0], blb[ni][1], blb[ni][2], blb[ni][3], rb + BHL);
            }
#pragma unroll
            for (int mi = 0; mi < 2; mi++)
#pragma unroll
                for (int nj = 0; nj < NJ; nj++)
                    MMA_BF16(acc[mi][nj], ahb[mi], bhb[nj >> 1][nj & 1], bhb[nj >> 1][(nj & 1) + 2]);
#pragma unroll
            for (int mi = 0; mi < 2; mi++)
#pragma unroll
                for (int nj = 0; nj < NJ; nj++)
                    MMA_BF16(acc[mi][nj], ahb[mi], blb[nj >> 1][nj & 1], blb[nj >> 1][(nj & 1) + 2]);
#pragma unroll
            for (int mi = 0; mi < 2; mi++)
#pragma unroll
                for (int nj = 0; nj < NJ; nj++)
                    MMA_BF16(acc[mi][nj], alb[mi], bhb[nj >> 1][nj & 1], bhb[nj >> 1][(nj & 1) + 2]);
        }
    }

    // ---------------- epilogue ------------------------------------------------
    const int gr = lane >> 2, gc = lane & 3;
    const bool second = DUAL && (m0 >= Dm);
#pragma unroll
    for (int mi = 0; mi < 2; mi++) {
#pragma unroll
        for (int half = 0; half < 2; half++) {
            const int m = m0 + wm + mi * 16 + gr + half * 8;
            const int mrow = second ? (m - Dm) : m;
            float bm = 0.0f;
            if ((EPI == 1 || EPI == 2) && BIASROW) bm = bias[m];
#pragma unroll
            for (int nj = 0; nj < NJ; nj++) {
                const int n = n0 + wn + nj * 8 + 2 * gc;
                float v0 = acc[mi][nj][half * 2 + 0];
                float v1 = acc[mi][nj][half * 2 + 1];
                if (EPI == 1 || EPI == 2) {
                    if (BIASROW) { v0 += bm; v1 += bm; }
                    else         { v0 += bias[n]; v1 += bias[n + 1]; }
                }
                if (EPI == 2 || (DUAL && second)) {
                    v0 *= sigmoidf_(v0); v1 *= sigmoidf_(v1);
                }
                if (EPI == 3) {
                    v0 = fmaxf(v0, 0.0f) + log1pf(expf(-fabsf(v0)));
                    v1 = fmaxf(v1, 0.0f) + log1pf(expf(-fabsf(v1)));
                }
                size_t idx = (size_t)mrow * Nn + n;
                const bool wf = WF32 && !(DUAL && second);
                const bool ws = (WSPLIT && !DUAL) || (DUAL && second);
                if (wf) *(float2*)&Cf[idx] = make_float2(v0, v1);
                if (ws) {
                    bf16 h0 = __float2bfloat16(v0);
                    bf16 h1 = __float2bfloat16(v1);
                    __nv_bfloat162 hh; hh.x = h0; hh.y = h1;
                    __nv_bfloat162 ll;
                    ll.x = __float2bfloat16(v0 - __bfloat162float(h0));
                    ll.y = __float2bfloat16(v1 - __bfloat162float(h1));
                    *(__nv_bfloat162*)&Chi[idx] = hh;
                    *(__nv_bfloat162*)&Clo[idx] = ll;
                }
            }
        }
    }
}

// ---------------- B/C projections: [L,D] @ [D,16] ---------------------------
__global__ void __launch_bounds__(256) bc_kernel(const float* __restrict__ Xc,
                                                 const float* __restrict__ WB,
                                                 const float* __restrict__ WC,
                                                 float* __restrict__ Bo,
                                                 float* __restrict__ Co) {
    __shared__ float row[Dm];
    const int l = blockIdx.x;
    for (int k = threadIdx.x; k < Dm; k += 256) row[k] = Xc[(size_t)l * Dm + k];
    __syncthreads();
    const int part = threadIdx.x & 7;
    const int out = threadIdx.x >> 3;   // 0..31
    const int n = out & 15;
    const float* W = (out < 16) ? WB : WC;
    float s = 0.0f;
    for (int k = part; k < Dm; k += 8) s = fmaf(row[k], W[k * Ns + n], s);
#pragma unroll
    for (int off = 4; off; off >>= 1) s += __shfl_down_sync(0xffffffffu, s, off, 8);
    if (part == 0) {
        if (out < 16) Bo[l * Ns + n] = s;
        else          Co[l * Ns + n] = s;
    }
}

// ---------------- selective scan v4: round-6 geometry, FMA-only exp ----------
// Thread per (d,n): grid 128 x 128 threads (8 d x 16 n per block).
__global__ void __launch_bounds__(128) scan_kernel(const float* __restrict__ delta,
                                                   const float* __restrict__ Xc,
                                                   const float* __restrict__ Bm,
                                                   const float* __restrict__ Cm,
                                                   const float* __restrict__ Alog,
                                                   bf16* __restrict__ Yhi,
                                                   bf16* __restrict__ Ylo) {
    const int n = threadIdx.x & 15;
    const int d = blockIdx.x * 8 + (threadIdx.x >> 4);
    const float c = expf(Alog[d * Ns + n]);   // once per thread
    float h = 0.0f;
    for (int l = 0; l < Dm; l++) {
        const size_t ix = (size_t)l * Dm + d;
        float de = delta[ix];
        float xv = Xc[ix];
        float bv = Bm[l * Ns + n];
        float cv = Cm[l * Ns + n];
        float e = exp_fma(-de * c);           // FMA pipe, no MUFU
        h = fmaf(e, h, de * xv * bv);
        float pr = h * cv;
#pragma unroll
        for (int off = 8; off; off >>= 1)
            pr += __shfl_down_sync(0xffffffffu, pr, off, 16);
        if (n == 0) {
            bf16 hh = __float2bfloat16(pr);
            Yhi[ix] = hh;
            Ylo[ix] = __float2bfloat16(pr - __bfloat162float(hh));
        }
    }
}

// ---------------- launch ------------------------------------------------------
extern "C" void kernel_launch(void* const* d_in, const int* in_sizes, int n_in,
                              void* d_out, int out_size) {
    const float* x    = (const float*)d_in[0];
    const float* Wp   = (const float*)d_in[1];
    const float* bp   = (const float*)d_in[2];
    const float* cw   = (const float*)d_in[3];
    const float* cb   = (const float*)d_in[4];
    const float* Alog = (const float*)d_in[5];
    const float* Wd   = (const float*)d_in[6];
    const float* WB   = (const float*)d_in[7];
    const float* WC   = (const float*)d_in[8];
    float* out = (float*)d_out;

    bf16 *xhi, *xlo, *Wphi, *Wplo, *cwhi, *cwlo, *WdThi, *WdTlo;
    bf16 *xghi, *xglo, *cBhi, *cBlo, *xchi, *xclo, *yhi, *ylo, *thi, *tlo;
    float *p0, *xc, *del, *Bm, *Cm;
    cudaGetSymbolAddress((void**)&xhi, g_xhi);   cudaGetSymbolAddress((void**)&xlo, g_xlo);
    cudaGetSymbolAddress((void**)&Wphi, g_Wphi); cudaGetSymbolAddress((void**)&Wplo, g_Wplo);
    cudaGetSymbolAddress((void**)&cwhi, g_cwhi); cudaGetSymbolAddress((void**)&cwlo, g_cwlo);
    cudaGetSymbolAddress((void**)&WdThi, g_WdThi); cudaGetSymbolAddress((void**)&WdTlo, g_WdTlo);
    cudaGetSymbolAddress((void**)&xghi, g_xghi); cudaGetSymbolAddress((void**)&xglo, g_xglo);
    cudaGetSymbolAddress((void**)&cBhi, g_cBhi); cudaGetSymbolAddress((void**)&cBlo, g_cBlo);
    cudaGetSymbolAddress((void**)&xchi, g_xchi); cudaGetSymbolAddress((void**)&xclo, g_xclo);
    cudaGetSymbolAddress((void**)&yhi, g_yhi);   cudaGetSymbolAddress((void**)&ylo, g_ylo);
    cudaGetSymbolAddress((void**)&thi, g_thi);   cudaGetSymbolAddress((void**)&tlo, g_tlo);
    cudaGetSymbolAddress((void**)&p0, g_p0);
    cudaGetSymbolAddress((void**)&xc, g_xc);
    cudaGetSymbolAddress((void**)&del, g_delta);
    cudaGetSymbolAddress((void**)&Bm, g_Bm);
    cudaGetSymbolAddress((void**)&Cm, g_Cm);

    const int SMEM128 = 3 * 65536;  // proj: TM=128,TN=128, 3 buffers
    const int SMEM64  = 4 * 49152;  // squares: TM=128,TN=64, 4 buffers
    cudaFuncSetAttribute(gemm_mma<512, 128, 128, 1, false, true,  true,  true>,  cudaFuncAttributeMaxDynamicSharedMemorySize, SMEM128);
    cudaFuncSetAttribute(gemm_mma<256, 128, 64,  2, true,  true,  true,  false>, cudaFuncAttributeMaxDynamicSharedMemorySize, SMEM64);
    cudaFuncSetAttribute(gemm_mma<256, 128, 64,  3, false, true,  false, false>, cudaFuncAttributeMaxDynamicSharedMemorySize, SMEM64);
    cudaFuncSetAttribute(gemm_mma<256, 128, 64,  0, false, false, true,  false>, cudaFuncAttributeMaxDynamicSharedMemorySize, SMEM64);
    cudaFuncSetAttribute(gemm_mma<256, 128, 64,  1, false, true,  false, false>, cudaFuncAttributeMaxDynamicSharedMemorySize, SMEM64);

    // #1..#3: splits needed by the proj GEMM
    split_k<<<(2 * Dm * Dm) / 2048, 256>>>(x, xhi, xlo, 2 * Dm * Dm);
    split_k<<<(Dm * Dm) / 2048, 256>>>(Wp, Wphi, Wplo, Dm * Dm);
    transpose_split_k<<<dim3(32, 32), dim3(32, 8)>>>(Wd, WdThi, WdTlo);

    // #4 (ncu slot, control): fused input projections, M=2048, 128x128, 512 thr
    gemm_mma<512, 128, 128, 1, false, true, true, true><<<dim3(8, 16), 512, SMEM128>>>(
        xhi, xlo, Wphi, Wplo, bp, p0, xghi, xglo, Dm, Dm);

    // conv operand prep
    split_k<<<(Dm * KC) / 2048, 256>>>(cw, cwhi, cwlo, Dm * KC);
    conv_b_build<<<dim3(32, 32), 256>>>(p0, cBhi, cBlo);

    // conv as GEMM (K = 3072), 128x64 tiles, 256 thr
    gemm_mma<256, 128, 64, 2, true, true, true, false><<<dim3(16, 8), 256, SMEM64>>>(
        cwhi, cwlo, cBhi, cBlo, cb, xc, xchi, xclo, Dm, KC);

    // delta = softplus(xc @ W_delta)   [exact round-6 epilogue, no WQ]
    gemm_mma<256, 128, 64, 3, false, true, false, false><<<dim3(16, 8), 256, SMEM64>>>(
        xchi, xclo, WdThi, WdTlo, nullptr, del, nullptr, nullptr, Dm, Dm);

    // B, C projections + scan
    bc_kernel<<<Dm, 256>>>(xc, WB, WC, Bm, Cm);
    scan_kernel<<<Dm / 8, 128>>>(del, xc, Bm, Cm, Alog, yhi, ylo);

    // t = y @ xg^T
    gemm_mma<256, 128, 64, 0, false, false, true, false><<<dim3(16, 8), 256, SMEM64>>>(
        yhi, ylo, xghi, xglo, nullptr, nullptr, thi, tlo, Dm, Dm);

    // out = t @ Wp^T + b
    gemm_mma<256, 128, 64, 1, false, true, false, false><<<dim3(16, 8), 256, SMEM64>>>(
        thi, tlo, Wphi, Wplo, bp, out, nullptr, nullptr, Dm, Dm);
}

// round 10
// speedup vs baseline: 1.5060x; 1.2233x over previous
#include <cuda_runtime.h>
#include <cuda_bf16.h>
#include <math.h>
#include <stdint.h>

constexpr int Dm = 1024;   // dim == seq len L
constexpr int Ns = 16;     // SSM state size
constexpr int KC = 3 * Dm; // conv GEMM K = 3072

typedef __nv_bfloat16 bf16;

// ---------------- scratch (static device globals: allocation-free) ----------
__device__ bf16 g_xhi[2 * Dm * Dm], g_xlo[2 * Dm * Dm];
__device__ bf16 g_Wphi[Dm * Dm],   g_Wplo[Dm * Dm];
__device__ bf16 g_cwhi[Dm * KC],   g_cwlo[Dm * KC];
__device__ bf16 g_WdThi[Dm * Dm],  g_WdTlo[Dm * Dm];
__device__ float g_p0[Dm * Dm];
__device__ bf16 g_xghi[Dm * Dm],   g_xglo[Dm * Dm];
__device__ bf16 g_cBhi[Dm * KC],   g_cBlo[Dm * KC];
__device__ float g_xc[Dm * Dm];
__device__ bf16 g_xchi[Dm * Dm],   g_xclo[Dm * Dm];
__device__ float g_delta[Dm * Dm];
__device__ float g_Bm[Dm * Ns], g_Cm[Dm * Ns];
__device__ bf16 g_yhi[Dm * Dm],    g_ylo[Dm * Dm];
__device__ bf16 g_thi[Dm * Dm],    g_tlo[Dm * Dm];

__device__ __forceinline__ float sigmoidf_(float x) {
    return 1.0f / (1.0f + expf(-x));
}

__device__ __forceinline__ uint32_t smem_u32(const void* p) {
    uint32_t a;
    asm("{ .reg .u64 t; cvta.to.shared.u64 t, %1; cvt.u32.u64 %0, t; }" : "=r"(a) : "l"(p));
    return a;
}

#define SWZ(x) ((x) ^ (((x) >> 3) & 0x70))

__device__ __forceinline__ void cpa16(uint32_t dst, const void* src) {
    asm volatile("cp.async.cg.shared.global [%0], [%1], 16;" :: "r"(dst), "l"(src));
}

#define MMA_BF16(c, a, b0, b1)                                                   \
    asm volatile(                                                                \
        "mma.sync.aligned.m16n8k16.row.col.f32.bf16.bf16.f32 "                   \
        "{%0,%1,%2,%3},{%4,%5,%6,%7},{%8,%9},{%0,%1,%2,%3};"                     \
        : "+f"(c[0]), "+f"(c[1]), "+f"(c[2]), "+f"(c[3])                         \
        : "r"(a[0]), "r"(a[1]), "r"(a[2]), "r"(a[3]), "r"(b0), "r"(b1))

#define LDSM_X4(r0, r1, r2, r3, addr)                                            \
    asm volatile("ldmatrix.sync.aligned.m8n8.x4.shared.b16 {%0,%1,%2,%3}, [%4];" \
        : "=r"(r0), "=r"(r1), "=r"(r2), "=r"(r3) : "r"(addr))

// ---------------- fp32 -> (hi,lo) bf16 split (vectorized 16B stores) --------
__global__ void __launch_bounds__(256) split_k(const float* __restrict__ in,
                                               bf16* __restrict__ hi,
                                               bf16* __restrict__ lo, int n) {
    int i = (blockIdx.x * 256 + threadIdx.x) * 8;
    if (i >= n) return;
    float4 v0 = *(const float4*)(in + i);
    float4 v1 = *(const float4*)(in + i + 4);
    float vv[8] = {v0.x, v0.y, v0.z, v0.w, v1.x, v1.y, v1.z, v1.w};
    __nv_bfloat162 hb[4], lb[4];
#pragma unroll
    for (int j = 0; j < 4; j++) {
        bf16 h0 = __float2bfloat16(vv[2 * j]);
        bf16 h1 = __float2bfloat16(vv[2 * j + 1]);
        hb[j].x = h0; hb[j].y = h1;
        lb[j].x = __float2bfloat16(vv[2 * j] - __bfloat162float(h0));
        lb[j].y = __float2bfloat16(vv[2 * j + 1] - __bfloat162float(h1));
    }
    *(int4*)(hi + i) = *(int4*)hb;
    *(int4*)(lo + i) = *(int4*)lb;
}

// ---------------- transpose + split (for W_delta) ---------------------------
__global__ void __launch_bounds__(256) transpose_split_k(const float* __restrict__ In,
                                                         bf16* __restrict__ hi,
                                                         bf16* __restrict__ lo) {
    __shared__ float t[32][33];
    int x0 = blockIdx.x * 32, y0 = blockIdx.y * 32;
    int tx = threadIdx.x;
    for (int j = threadIdx.y; j < 32; j += 8)
        t[j][tx] = In[(y0 + j) * Dm + x0 + tx];
    __syncthreads();
    for (int j = threadIdx.y; j < 32; j += 8) {
        float v = t[tx][j];
        bf16 h = __float2bfloat16(v);
        size_t idx = (size_t)(x0 + j) * Dm + y0 + tx;
        hi[idx] = h;
        lo[idx] = __float2bfloat16(v - __bfloat162float(h));
    }
}

// ---------------- build conv B matrix: B[d, i*3+kk] = p0[i, d-1+kk] ----------
__global__ void __launch_bounds__(256) conv_b_build(const float* __restrict__ P0,
                                                    bf16* __restrict__ hi,
                                                    bf16* __restrict__ lo) {
    __shared__ float Xs[32][35];
    int d0 = blockIdx.x * 32, i0 = blockIdx.y * 32;
    int tid = threadIdx.x;
    for (int idx = tid; idx < 32 * 34; idx += 256) {
        int r = idx / 34, c = idx % 34;
        int gd = d0 - 1 + c;
        Xs[r][c] = (gd >= 0 && gd < Dm) ? P0[(size_t)(i0 + r) * Dm + gd] : 0.0f;
    }
    __syncthreads();
    int i = tid & 31;
    for (int dl = tid >> 5; dl < 32; dl += 8) {
        size_t base = (size_t)(d0 + dl) * KC + (size_t)(i0 + i) * 3;
#pragma unroll
        for (int kk = 0; kk < 3; kk++) {
            float x = Xs[i][dl + kk];
            bf16 h = __float2bfloat16(x);
            hi[base + kk] = h;
            lo[base + kk] = __float2bfloat16(x - __bfloat162float(h));
        }
    }
}

// ---------------- bf16-split HMMA GEMM, deep cp.async pipeline ---------------
// C[m,n] = sum_k A[m,k]*B[n,k]; A=Ah+Al, B=Bh+Bl; C ~= Ah*Bh + Ah*Bl + Al*Bh.
// NT threads, CTA tile TM x TN, K-block 64, NBUF buffers, 1 barrier/stage.
template <int NT, int TM, int TN, int EPI, bool BIASROW, bool WF32, bool WSPLIT,
          bool DUAL>
__global__ void __launch_bounds__(NT, 1)
gemm_mma(const bf16* __restrict__ Ah, const bf16* __restrict__ Al,
         const bf16* __restrict__ Bh, const bf16* __restrict__ Bl,
         const float* __restrict__ bias,
         float* __restrict__ Cf, bf16* __restrict__ Chi, bf16* __restrict__ Clo,
         int Nn, int K)
{
    constexpr int OFF_AL = TM * 128;
    constexpr int OFF_BH = TM * 256;
    constexpr int BHL = TN * 128;
    constexpr int STAGEB = (TM + TN) * 256;
    constexpr int NBUF = (STAGEB >= 65536) ? 3 : 4;
    constexpr int DEPTH = NBUF - 1;
    constexpr int WARPS_M = TM / 32;
    constexpr int NWARP = NT / 32;
    constexpr int WN = TN / (NWARP / WARPS_M);
    constexpr int NG = WN / 16;
    constexpr int NJ = WN / 8;

    extern __shared__ __align__(1024) char dyns[];
    const int tid = threadIdx.x;
    const int lane = tid & 31, warp = tid >> 5;
    const int m0 = blockIdx.y * TM, n0 = blockIdx.x * TN;
    const uint32_t dbase = smem_u32(dyns);
    const int S = K >> 6;

    float acc[2][NJ][4];
#pragma unroll
    for (int a = 0; a < 2; a++)
#pragma unroll
        for (int b = 0; b < NJ; b++)
#pragma unroll
            for (int c = 0; c < 4; c++) acc[a][b][c] = 0.0f;

    auto load_stage = [&](int s) {
        const uint32_t sb = dbase + (s % NBUF) * STAGEB;
        const int k0 = s << 6;
#pragma unroll
        for (int i = 0; i < TM * 8 / NT; i++) {
            int q = tid + i * NT;
            int r = q >> 3, c = q & 7;
            uint32_t so = SWZ((uint32_t)(r * 128 + c * 16));
            size_t ga = (size_t)(m0 + r) * K + k0 + c * 8;
            cpa16(sb + so, Ah + ga);
            cpa16(sb + OFF_AL + so, Al + ga);
        }
#pragma unroll
        for (int i = 0; i < TN * 8 / NT; i++) {
            int q = tid + i * NT;
            int r = q >> 3, c = q & 7;
            uint32_t so = SWZ((uint32_t)(r * 128 + c * 16));
            size_t gb = (size_t)(n0 + r) * K + k0 + c * 8;
            cpa16(sb + OFF_BH + so, Bh + gb);
            cpa16(sb + OFF_BH + BHL + so, Bl + gb);
        }
        asm volatile("cp.async.commit_group;" ::: "memory");
    };

#pragma unroll
    for (int s = 0; s < DEPTH; s++) load_stage(s);

    const int wm = (warp % WARPS_M) * 32, wn = (warp / WARPS_M) * WN;
    const uint32_t frow = (lane & 7) + ((lane >> 3) & 1) * 8;
    const uint32_t fxor = (frow & 7) << 4;
    const uint32_t fcol = (lane >> 4) << 4;

    for (int s = 0; s < S; s++) {
        asm volatile("cp.async.wait_group %0;" :: "n"(DEPTH - 1) : "memory");
        __syncthreads();
        if (s + DEPTH < S) load_stage(s + DEPTH);
        else asm volatile("cp.async.commit_group;" ::: "memory");

        const uint32_t sb = dbase + (s % NBUF) * STAGEB;
#pragma unroll
        for (int ks = 0; ks < 4; ks++) {
            const uint32_t kc = (uint32_t)(ks * 32 + fcol) ^ fxor;
            uint32_t ahb[2][4], alb[2][4], bhb[NG][4], blb[NG][4];
#pragma unroll
            for (int mi = 0; mi < 2; mi++) {
                uint32_t ra = sb + (wm + mi * 16 + frow) * 128 + kc;
                LDSM_X4(ahb[mi][0], ahb[mi][1], ahb[mi][2], ahb[mi][3], ra);
                LDSM_X4(alb[mi][0], alb[mi][1], alb[mi][2], alb[mi][3], ra + OFF_AL);
            }
#pragma unroll
            for (int ni = 0; ni < NG; ni++) {
                uint32_t rb = sb + OFF_BH + (wn + ni * 16 + frow) * 128 + kc;
                LDSM_X4(bhb[ni][0], bhb[ni][1], bhb[ni][2], bhb[ni][3], rb);
                LDSM_X4(blb[ni][0], blb[ni][1], blb[ni][2], blb[ni][3], rb + BHL);
            }
#pragma unroll
            for (int mi = 0; mi < 2; mi++)
#pragma unroll
                for (int nj = 0; nj < NJ; nj++)
                    MMA_BF16(acc[mi][nj], ahb[mi], bhb[nj >> 1][nj & 1], bhb[nj >> 1][(nj & 1) + 2]);
#pragma unroll
            for (int mi = 0; mi < 2; mi++)
#pragma unroll
                for (int nj = 0; nj < NJ; nj++)
                    MMA_BF16(acc[mi][nj], ahb[mi], blb[nj >> 1][nj & 1], blb[nj >> 1][(nj & 1) + 2]);
#pragma unroll
            for (int mi = 0; mi < 2; mi++)
#pragma unroll
                for (int nj = 0; nj < NJ; nj++)
                    MMA_BF16(acc[mi][nj], alb[mi], bhb[nj >> 1][nj & 1], bhb[nj >> 1][(nj & 1) + 2]);
        }
    }

    // ---------------- epilogue ------------------------------------------------
    const int gr = lane >> 2, gc = lane & 3;
    const bool second = DUAL && (m0 >= Dm);
#pragma unroll
    for (int mi = 0; mi < 2; mi++) {
#pragma unroll
        for (int half = 0; half < 2; half++) {
            const int m = m0 + wm + mi * 16 + gr + half * 8;
            const int mrow = second ? (m - Dm) : m;
            float bm = 0.0f;
            if ((EPI == 1 || EPI == 2) && BIASROW) bm = bias[m];
#pragma unroll
            for (int nj = 0; nj < NJ; nj++) {
                const int n = n0 + wn + nj * 8 + 2 * gc;
                float v0 = acc[mi][nj][half * 2 + 0];
                float v1 = acc[mi][nj][half * 2 + 1];
                if (EPI == 1 || EPI == 2) {
                    if (BIASROW) { v0 += bm; v1 += bm; }
                    else         { v0 += bias[n]; v1 += bias[n + 1]; }
                }
                if (EPI == 2 || (DUAL && second)) {
                    v0 *= sigmoidf_(v0); v1 *= sigmoidf_(v1);
                }
                if (EPI == 3) {
                    v0 = fmaxf(v0, 0.0f) + log1pf(expf(-fabsf(v0)));
                    v1 = fmaxf(v1, 0.0f) + log1pf(expf(-fabsf(v1)));
                }
                size_t idx = (size_t)mrow * Nn + n;
                const bool wf = WF32 && !(DUAL && second);
                const bool ws = (WSPLIT && !DUAL) || (DUAL && second);
                if (wf) *(float2*)&Cf[idx] = make_float2(v0, v1);
                if (ws) {
                    bf16 h0 = __float2bfloat16(v0);
                    bf16 h1 = __float2bfloat16(v1);
                    __nv_bfloat162 hh; hh.x = h0; hh.y = h1;
                    __nv_bfloat162 ll;
                    ll.x = __float2bfloat16(v0 - __bfloat162float(h0));
                    ll.y = __float2bfloat16(v1 - __bfloat162float(h1));
                    *(__nv_bfloat162*)&Chi[idx] = hh;
                    *(__nv_bfloat162*)&Clo[idx] = ll;
                }
            }
        }
    }
}

// ---------------- B/C projections: [L,D] @ [D,16] ---------------------------
__global__ void __launch_bounds__(256) bc_kernel(const float* __restrict__ Xc,
                                                 const float* __restrict__ WB,
                                                 const float* __restrict__ WC,
                                                 float* __restrict__ Bo,
                                                 float* __restrict__ Co) {
    __shared__ float row[Dm];
    const int l = blockIdx.x;
    for (int k = threadIdx.x; k < Dm; k += 256) row[k] = Xc[(size_t)l * Dm + k];
    __syncthreads();
    const int part = threadIdx.x & 7;
    const int out = threadIdx.x >> 3;   // 0..31
    const int n = out & 15;
    const float* W = (out < 16) ? WB : WC;
    float s = 0.0f;
    for (int k = part; k < Dm; k += 8) s = fmaf(row[k], W[k * Ns + n], s);
#pragma unroll
    for (int off = 4; off; off >>= 1) s += __shfl_down_sync(0xffffffffu, s, off, 8);
    if (part == 0) {
        if (out < 16) Bo[l * Ns + n] = s;
        else          Co[l * Ns + n] = s;
    }
}

// ---------------- selective scan (round-6 v1: __expf, + load prefetch) -------
// Thread per (d,n): grid 128 x 128 threads (8 d x 16 n per block).
__global__ void __launch_bounds__(128) scan_kernel(const float* __restrict__ delta,
                                                   const float* __restrict__ Xc,
                                                   const float* __restrict__ Bm,
                                                   const float* __restrict__ Cm,
                                                   const float* __restrict__ Alog,
                                                   bf16* __restrict__ Yhi,
                                                   bf16* __restrict__ Ylo) {
    const int n = threadIdx.x & 15;
    const int d = blockIdx.x * 8 + (threadIdx.x >> 4);
    const float a = -expf(Alog[d * Ns + n]);
    float h = 0.0f;

    // prefetch l=0
    float de = delta[d];
    float xv = Xc[d];
    float bv = Bm[n];
    float cv = Cm[n];

    for (int l = 0; l < Dm; l++) {
        const size_t ix = (size_t)l * Dm + d;
        // prefetch next iteration's operands (overlaps exp/fma chain)
        float de_n = 0.f, xv_n = 0.f, bv_n = 0.f, cv_n = 0.f;
        if (l + 1 < Dm) {
            const size_t ixn = ix + Dm;
            de_n = delta[ixn];
            xv_n = Xc[ixn];
            bv_n = Bm[(l + 1) * Ns + n];
            cv_n = Cm[(l + 1) * Ns + n];
        }
        float e = __expf(de * a);
        h = fmaf(e, h, de * xv * bv);
        float pr = h * cv;
#pragma unroll
        for (int off = 8; off; off >>= 1)
            pr += __shfl_down_sync(0xffffffffu, pr, off, 16);
        if (n == 0) {
            bf16 hh = __float2bfloat16(pr);
            Yhi[ix] = hh;
            Ylo[ix] = __float2bfloat16(pr - __bfloat162float(hh));
        }
        de = de_n; xv = xv_n; bv = bv_n; cv = cv_n;
    }
}

// ---------------- launch ------------------------------------------------------
extern "C" void kernel_launch(void* const* d_in, const int* in_sizes, int n_in,
                              void* d_out, int out_size) {
    const float* x    = (const float*)d_in[0];
    const float* Wp   = (const float*)d_in[1];
    const float* bp   = (const float*)d_in[2];
    const float* cw   = (const float*)d_in[3];
    const float* cb   = (const float*)d_in[4];
    const float* Alog = (const float*)d_in[5];
    const float* Wd   = (const float*)d_in[6];
    const float* WB   = (const float*)d_in[7];
    const float* WC   = (const float*)d_in[8];
    float* out = (float*)d_out;

    bf16 *xhi, *xlo, *Wphi, *Wplo, *cwhi, *cwlo, *WdThi, *WdTlo;
    bf16 *xghi, *xglo, *cBhi, *cBlo, *xchi, *xclo, *yhi, *ylo, *thi, *tlo;
    float *p0, *xc, *del, *Bm, *Cm;
    cudaGetSymbolAddress((void**)&xhi, g_xhi);   cudaGetSymbolAddress((void**)&xlo, g_xlo);
    cudaGetSymbolAddress((void**)&Wphi, g_Wphi); cudaGetSymbolAddress((void**)&Wplo, g_Wplo);
    cudaGetSymbolAddress((void**)&cwhi, g_cwhi); cudaGetSymbolAddress((void**)&cwlo, g_cwlo);
    cudaGetSymbolAddress((void**)&WdThi, g_WdThi); cudaGetSymbolAddress((void**)&WdTlo, g_WdTlo);
    cudaGetSymbolAddress((void**)&xghi, g_xghi); cudaGetSymbolAddress((void**)&xglo, g_xglo);
    cudaGetSymbolAddress((void**)&cBhi, g_cBhi); cudaGetSymbolAddress((void**)&cBlo, g_cBlo);
    cudaGetSymbolAddress((void**)&xchi, g_xchi); cudaGetSymbolAddress((void**)&xclo, g_xclo);
    cudaGetSymbolAddress((void**)&yhi, g_yhi);   cudaGetSymbolAddress((void**)&ylo, g_ylo);
    cudaGetSymbolAddress((void**)&thi, g_thi);   cudaGetSymbolAddress((void**)&tlo, g_tlo);
    cudaGetSymbolAddress((void**)&p0, g_p0);
    cudaGetSymbolAddress((void**)&xc, g_xc);
    cudaGetSymbolAddress((void**)&del, g_delta);
    cudaGetSymbolAddress((void**)&Bm, g_Bm);
    cudaGetSymbolAddress((void**)&Cm, g_Cm);

    const int SMEM128 = 3 * 65536;  // proj: TM=128,TN=128, 3 buffers
    const int SMEM64  = 4 * 49152;  // squares: TM=128,TN=64, 4 buffers
    cudaFuncSetAttribute(gemm_mma<512, 128, 128, 1, false, true,  true,  true>,  cudaFuncAttributeMaxDynamicSharedMemorySize, SMEM128);
    cudaFuncSetAttribute(gemm_mma<256, 128, 64,  2, true,  true,  true,  false>, cudaFuncAttributeMaxDynamicSharedMemorySize, SMEM64);
    cudaFuncSetAttribute(gemm_mma<256, 128, 64,  3, false, true,  false, false>, cudaFuncAttributeMaxDynamicSharedMemorySize, SMEM64);
    cudaFuncSetAttribute(gemm_mma<256, 128, 64,  0, false, false, true,  false>, cudaFuncAttributeMaxDynamicSharedMemorySize, SMEM64);
    cudaFuncSetAttribute(gemm_mma<256, 128, 64,  1, false, true,  false, false>, cudaFuncAttributeMaxDynamicSharedMemorySize, SMEM64);

    // #1..#3: splits needed by the proj GEMM
    split_k<<<(2 * Dm * Dm) / 2048, 256>>>(x, xhi, xlo, 2 * Dm * Dm);
    split_k<<<(Dm * Dm) / 2048, 256>>>(Wp, Wphi, Wplo, Dm * Dm);
    transpose_split_k<<<dim3(32, 32), dim3(32, 8)>>>(Wd, WdThi, WdTlo);

    // #4 (ncu slot, control): fused input projections, M=2048, 128x128, 512 thr
    gemm_mma<512, 128, 128, 1, false, true, true, true><<<dim3(8, 16), 512, SMEM128>>>(
        xhi, xlo, Wphi, Wplo, bp, p0, xghi, xglo, Dm, Dm);

    // conv operand prep
    split_k<<<(Dm * KC) / 2048, 256>>>(cw, cwhi, cwlo, Dm * KC);
    conv_b_build<<<dim3(32, 32), 256>>>(p0, cBhi, cBlo);

    // conv as GEMM (K = 3072), 128x64 tiles, 256 thr
    gemm_mma<256, 128, 64, 2, true, true, true, false><<<dim3(16, 8), 256, SMEM64>>>(
        cwhi, cwlo, cBhi, cBlo, cb, xc, xchi, xclo, Dm, KC);

    // delta = softplus(xc @ W_delta)
    gemm_mma<256, 128, 64, 3, false, true, false, false><<<dim3(16, 8), 256, SMEM64>>>(
        xchi, xclo, WdThi, WdTlo, nullptr, del, nullptr, nullptr, Dm, Dm);

    // B, C projections + scan (round-6 scan restored)
    bc_kernel<<<Dm, 256>>>(xc, WB, WC, Bm, Cm);
    scan_kernel<<<Dm / 8, 128>>>(del, xc, Bm, Cm, Alog, yhi, ylo);

    // t = y @ xg^T
    gemm_mma<256, 128, 64, 0, false, false, true, false><<<dim3(16, 8), 256, SMEM64>>>(
        yhi, ylo, xghi, xglo, nullptr, nullptr, thi, tlo, Dm, Dm);

    // out = t @ Wp^T + b
    gemm_mma<256, 128, 64, 1, false, true, false, false><<<dim3(16, 8), 256, SMEM64>>>(
        thi, tlo, Wphi, Wplo, bp, out, nullptr, nullptr, Dm, Dm);
}